// round 7
// baseline (speedup 1.0000x reference)
#include <cuda_runtime.h>
#include <math_constants.h>
#include <math.h>

#define BSZ 4
#define NP  2048
#define NT  64            // 64 tiles of 32 points
#define EPSF 1e-6f
#define INF  CUDART_INF_F

// ---------------- scratch ----------------
__device__ float2 g_pos[2][BSZ][NP];      // points sorted by x: real=0, fake=1
__device__ float g_knn[2][BSZ][NP * 3];   // sqrt'd 3NN (incl self)
__device__ float g_sel[14][14];           // selected order statistics
__device__ float g_hex_partial[256];
__device__ float g_feas_partial[256];

// ---------------- float<->sortable key ----------------
__device__ __forceinline__ unsigned fkey(float f) {
    unsigned u = __float_as_uint(f);
    return (u & 0x80000000u) ? ~u : (u | 0x80000000u);
}
__device__ __forceinline__ float unfkey(unsigned k) {
    unsigned u = (k & 0x80000000u) ? (k ^ 0x80000000u) : ~k;
    return __uint_as_float(u);
}

// ---------------- sort kernel: 8 blocks, sort each (type,batch) by x ----------------
__global__ void __launch_bounds__(1024) sort_kernel(const float* __restrict__ real_in,
                                                    const float* __restrict__ fake_in) {
    __shared__ unsigned skey[NP];
    __shared__ float sy[NP];
    int t = blockIdx.x >> 2;     // 0 real, 1 fake
    int b = blockIdx.x & 3;
    const float* base = (t ? fake_in : real_in) + b * NP * 3;
    int tid = threadIdx.x;
    for (int j = tid; j < NP; j += 1024) {
        skey[j] = fkey(base[j * 3]);
        sy[j] = base[j * 3 + 1];
    }
    __syncthreads();
    for (int k = 2; k <= NP; k <<= 1) {
        for (int jj = k >> 1; jj > 0; jj >>= 1) {
            for (int i = tid; i < NP; i += 1024) {
                int ix = i ^ jj;
                if (ix > i) {
                    unsigned ku = skey[i], kv = skey[ix];
                    bool up = ((i & k) == 0);
                    if ((ku > kv) == up) {
                        skey[i] = kv; skey[ix] = ku;
                        float yu = sy[i]; sy[i] = sy[ix]; sy[ix] = yu;
                    }
                }
            }
            __syncthreads();
        }
    }
    for (int j = tid; j < NP; j += 1024)
        g_pos[t][b][j] = make_float2(unfkey(skey[j]), sy[j]);
}

// ---------------- branch-free sorted inserts (FMNMX networks) ----------------
#define INS3(a0,a1,a2,d) do{ \
    float _m1 = fmaxf(a0,(d)), _m2 = fmaxf(a1,(d)); \
    a0 = fminf(a0,(d)); a1 = fminf(a1,_m1); a2 = fminf(a2,_m2); }while(0)

#define INS5(a0,a1,a2,a3,a4,d) do{ \
    float _m1 = fmaxf(a0,(d)), _m2 = fmaxf(a1,(d)), _m3 = fmaxf(a2,(d)), _m4 = fmaxf(a3,(d)); \
    a0 = fminf(a0,(d)); a1 = fminf(a1,_m1); a2 = fminf(a2,_m2); \
    a3 = fminf(a3,_m3); a4 = fminf(a4,_m4); }while(0)

// ---------------- warp k-min extraction ----------------
__device__ __forceinline__ float pop3(float& a0, float& a1, float& a2, int lane) {
    float bv = a0; int bl = lane;
#pragma unroll
    for (int off = 16; off; off >>= 1) {
        float ov = __shfl_down_sync(0xffffffffu, bv, off);
        int   ol = __shfl_down_sync(0xffffffffu, bl, off);
        if (ov < bv) { bv = ov; bl = ol; }
    }
    bv = __shfl_sync(0xffffffffu, bv, 0);
    bl = __shfl_sync(0xffffffffu, bl, 0);
    if (lane == bl) { a0 = a1; a1 = a2; a2 = INF; }
    return bv;
}
__device__ __forceinline__ float pop5(float& a0, float& a1, float& a2, float& a3, float& a4,
                                      int lane) {
    float bv = a0; int bl = lane;
#pragma unroll
    for (int off = 16; off; off >>= 1) {
        float ov = __shfl_down_sync(0xffffffffu, bv, off);
        int   ol = __shfl_down_sync(0xffffffffu, bl, off);
        if (ov < bv) { bv = ov; bl = ol; }
    }
    bv = __shfl_sync(0xffffffffu, bv, 0);
    bl = __shfl_sync(0xffffffffu, bl, 0);
    if (lane == bl) { a0 = a1; a1 = a2; a2 = a3; a3 = a4; a4 = INF; }
    return bv;
}

// ---------------- hex contribution (shared by loop + self-subtraction) ----------------
__device__ __forceinline__ void hex_contrib(float dx, float dy, float d2,
                                            float kth, float inv_sigma,
                                            float& wsum, float& wre, float& wim) {
    float d2e = d2 + EPSF;
    float dist = d2e * rsqrtf(d2e);
    float arg = (kth - dist) * inv_sigma;              // gate guarantees arg in (-18, ~10)
    float e = __expf(-arg);
    float w = __fdividef(1.0f, 1.0f + e);
    float c = dx;
    if (fabsf(c) < EPSF) c = c + EPSF;
    float n2 = fmaf(c, c, dy * dy);
    float inv = __fdividef(1.0f, n2);
    float un = (c * c - dy * dy) * inv;                // cos 2t
    float vn = (2.0f * c * dy) * inv;                  // sin 2t
    float re4 = un * un - vn * vn;                     // cos 4t
    float im4 = 2.0f * un * vn;                        // sin 4t
    wsum += w;
    wre = fmaf(w, re4, wre);
    wim = fmaf(w, im4, wim);
}

// ================ pairs kernel ================
// blocks [0,256): real kNN pruned; [256,512): fake kNN+hex pruned; [512,768): feas dense
__global__ void __launch_bounds__(256) pairs_kernel(const float* __restrict__ fake_in) {
    __shared__ float2 sxy[NP];
    __shared__ float srr[NP];
    __shared__ float s_acc[8];
    int bx = blockIdx.x;
    int warp = threadIdx.x >> 5, lane = threadIdx.x & 31;

    if (bx < 512) {
        int typ = bx >> 8;               // 0 real, 1 fake
        int bx2 = bx & 255;
        int b = bx2 >> 6;
        int i0 = ((bx2 & 63) * 8 + warp) * 4;      // 4 consecutive sorted points
        const float2* __restrict__ P = g_pos[typ][b];
        float qx[4], qy[4];
#pragma unroll
        for (int p = 0; p < 4; p++) { float2 t = P[i0 + p]; qx[p] = t.x; qy[p] = t.y; }
        float qxlo = qx[0], qxhi = qx[3];          // sorted order
        int t0 = i0 >> 5;                          // home tile (i0%4==0 -> all 4 in one tile)

        if (typ == 0) {
            // -------- real kNN: exact top-3 incl self via expanding-tile search --------
            float a[4][3];
#pragma unroll
            for (int p = 0; p < 4; p++) { a[p][0] = INF; a[p][1] = INF; a[p][2] = INF; }
#define PROC3(t) do{ \
    float2 pj = P[(t) * 32 + lane]; \
    _Pragma("unroll") \
    for (int p = 0; p < 4; p++) { \
        float dx = qx[p] - pj.x, dy = qy[p] - pj.y; \
        float d2 = fmaf(dx, dx, dy * dy); \
        INS3(a[p][0], a[p][1], a[p][2], d2); } }while(0)
            PROC3(t0);
            int tR = t0 + 1, tL = t0 - 1;
            while (true) {
                // T = upper bound on each point's current 3rd-smallest:
                // any lane's a2 bounds the warp 3rd-min (that lane alone has 3 values <= a2)
                float T = 0.0f;
#pragma unroll
                for (int p = 0; p < 4; p++) {
                    unsigned m = __reduce_min_sync(0xffffffffu, __float_as_uint(a[p][2]));
                    T = fmaxf(T, __uint_as_float(m));
                }
                bool okR = false, okL = false;
                if (tR < NT) { float g = P[tR * 32].x - qxhi;      okR = (g * g <= T); }
                if (tL >= 0) { float g = qxlo - P[tL * 32 + 31].x; okL = (g * g <= T); }
                if (!okR && !okL) break;
                if (okR) { PROC3(tR); tR++; }
                if (okL) { PROC3(tL); tL--; }
            }
#pragma unroll
            for (int p = 0; p < 4; p++) {
                float o0 = pop3(a[p][0], a[p][1], a[p][2], lane);
                float o1 = pop3(a[p][0], a[p][1], a[p][2], lane);
                float o2 = pop3(a[p][0], a[p][1], a[p][2], lane);
                if (lane == 0) {
                    float* dst = &g_knn[0][b][(i0 + p) * 3];
                    dst[0] = sqrtf(o0 + EPSF); dst[1] = sqrtf(o1 + EPSF); dst[2] = sqrtf(o2 + EPSF);
                }
            }
        } else {
            // -------- fake: exact top-5 incl self (kNN + kth), then weighted pass --------
            float a[4][5];
#pragma unroll
            for (int p = 0; p < 4; p++)
                { a[p][0]=INF; a[p][1]=INF; a[p][2]=INF; a[p][3]=INF; a[p][4]=INF; }
#define PROC5(t) do{ \
    float2 pj = P[(t) * 32 + lane]; \
    _Pragma("unroll") \
    for (int p = 0; p < 4; p++) { \
        float dx = qx[p] - pj.x, dy = qy[p] - pj.y; \
        float d2 = fmaf(dx, dx, dy * dy); \
        INS5(a[p][0], a[p][1], a[p][2], a[p][3], a[p][4], d2); } }while(0)
            PROC5(t0);
            int tR = t0 + 1, tL = t0 - 1;
            while (true) {
                float T = 0.0f;
#pragma unroll
                for (int p = 0; p < 4; p++) {
                    unsigned m = __reduce_min_sync(0xffffffffu, __float_as_uint(a[p][4]));
                    T = fmaxf(T, __uint_as_float(m));
                }
                bool okR = false, okL = false;
                if (tR < NT) { float g = P[tR * 32].x - qxhi;      okR = (g * g <= T); }
                if (tL >= 0) { float g = qxlo - P[tL * 32 + 31].x; okL = (g * g <= T); }
                if (!okR && !okL) break;
                if (okR) { PROC5(tR); tR++; }
                if (okL) { PROC5(tL); tL--; }
            }
            float kth[4], isg[4], lim2[4];
#pragma unroll
            for (int p = 0; p < 4; p++) {
                float o0 = pop5(a[p][0], a[p][1], a[p][2], a[p][3], a[p][4], lane);
                float o1 = pop5(a[p][0], a[p][1], a[p][2], a[p][3], a[p][4], lane);
                float o2 = pop5(a[p][0], a[p][1], a[p][2], a[p][3], a[p][4], lane);
                float o3 = pop5(a[p][0], a[p][1], a[p][2], a[p][3], a[p][4], lane); (void)o3;
                float o4 = pop5(a[p][0], a[p][1], a[p][2], a[p][3], a[p][4], lane);
                if (lane == 0) {   // kNN incl self: o0=0(self), o1, o2
                    float* dst = &g_knn[1][b][(i0 + p) * 3];
                    dst[0] = sqrtf(o0 + EPSF); dst[1] = sqrtf(o1 + EPSF); dst[2] = sqrtf(o2 + EPSF);
                }
                float kv = sqrtf(o4 + EPSF);       // 4th non-self neighbor
                float sg = fmaxf(0.1f * fmaxf(kv, EPSF), EPSF);
                kth[p] = kv;
                isg[p] = __fdividef(1.0f, sg);
                float lim = kv + 18.0f * sg;       // beyond: w <= sigmoid(-18), negligible
                lim2[p] = fmaf(lim, lim, -EPSF);
            }
            // pass 2: weighted orientation sums, pruned by fixed radius
            float ws[4] = {0.f,0.f,0.f,0.f}, wr[4] = {0.f,0.f,0.f,0.f}, wi[4] = {0.f,0.f,0.f,0.f};
            float T2 = fmaxf(fmaxf(lim2[0], lim2[1]), fmaxf(lim2[2], lim2[3]));
#define PROCH(t) do{ \
    float2 pj = P[(t) * 32 + lane]; \
    _Pragma("unroll") \
    for (int p = 0; p < 4; p++) { \
        float dx = qx[p] - pj.x, dy = qy[p] - pj.y; \
        float d2 = fmaf(dx, dx, dy * dy); \
        if (d2 <= lim2[p]) hex_contrib(dx, dy, d2, kth[p], isg[p], ws[p], wr[p], wi[p]); } }while(0)
            PROCH(t0);
            tR = t0 + 1; tL = t0 - 1;
            while (true) {
                bool okR = false, okL = false;
                if (tR < NT) { float g = P[tR * 32].x - qxhi;      okR = (g * g <= T2); }
                if (tL >= 0) { float g = qxlo - P[tL * 32 + 31].x; okL = (g * g <= T2); }
                if (!okR && !okL) break;
                if (okR) { PROCH(tR); tR++; }
                if (okL) { PROCH(tL); tL--; }
            }
#pragma unroll
            for (int p = 0; p < 4; p++) {
#pragma unroll
                for (int off = 16; off; off >>= 1) {
                    ws[p] += __shfl_down_sync(0xffffffffu, ws[p], off);
                    wr[p] += __shfl_down_sync(0xffffffffu, wr[p], off);
                    wi[p] += __shfl_down_sync(0xffffffffu, wi[p], off);
                }
            }
            if (lane == 0) {
                float psum = 0.0f;
#pragma unroll
                for (int p = 0; p < 4; p++) {
                    float ss = 0.0f, sr = 0.0f, si = 0.0f;   // subtract self exactly once
                    hex_contrib(0.0f, 0.0f, 0.0f, kth[p], isg[p], ss, sr, si);
                    float wsum = ws[p] - ss, wre = wr[p] - sr, wim = wi[p] - si;
                    psum += sqrtf(wre * wre + wim * wim) / fmaxf(wsum, EPSF);
                }
                s_acc[warp] = psum;
            }
            __syncthreads();
            if (threadIdx.x == 0) {
                float s = 0.0f;
                for (int w = 0; w < 8; w++) s += s_acc[w];
                g_hex_partial[bx2] = s;
            }
        }
    } else {
        // -------- feasibility: dense lower triangle (original order), 4 rows/warp --------
        int bx2 = bx - 512;
        int b = bx2 >> 6;
        int ibase = (bx2 & 63) * 32;
        const float* base = fake_in + b * NP * 3;
        for (int j = threadIdx.x; j < NP; j += 256) {
            sxy[j] = make_float2(base[j * 3], base[j * 3 + 1]);
            srr[j] = fabsf(base[j * 3 + 2]);
        }
        __syncthreads();
        float qx[4], qy[4], ri[4];
        int i0 = ibase + warp * 4;
#pragma unroll
        for (int p = 0; p < 4; p++) {
            float2 pp = sxy[i0 + p];
            qx[p] = pp.x; qy[p] = pp.y;
            ri[p] = srr[i0 + p] - 1e-4f;
        }
        float acc = 0.0f;
        int imax = i0 + 3;
        for (int j = lane; j < imax; j += 32) {
            float2 pj = sxy[j];
            float rj = srr[j];
#pragma unroll
            for (int p = 0; p < 4; p++) {
                if (j < i0 + p) {                      // strict lower triangle
                    float dx = qx[p] - pj.x, dy = qy[p] - pj.y;
                    float sq = fmaf(dx, dx, dy * dy);
                    float thr = ri[p] + rj;
                    if (sq > 0.0f && thr > 0.0f && sq < thr * thr)
                        acc += thr - sq * rsqrtf(sq);
                }
            }
        }
#pragma unroll
        for (int off = 16; off; off >>= 1)
            acc += __shfl_down_sync(0xffffffffu, acc, off);
        if (lane == 0) s_acc[warp] = acc;
        __syncthreads();
        if (threadIdx.x == 0) {
            float s = 0.0f;
            for (int w = 0; w < 8; w++) s += s_acc[w];
            g_feas_partial[bx2] = s;
        }
    }
}

// ---------------- radix select: one block per (array, rank), 1024 thr ----------------
#define XY10 409,410,2047,2048,4095,4096,6143,6144,7781,7782
#define Z14  409,410,819,820,2047,2048,4095,4096,6143,6144,7371,7372,7781,7782
#define K6   307,308,3071,3072,5835,5836
#define R10(x) x,x,x,x,x,x,x,x,x,x
#define R14(x) x,x,x,x,x,x,x,x,x,x,x,x,x,x
#define R6(x)  x,x,x,x,x,x
#define S10 0,1,2,3,4,5,6,7,8,9
#define S14 0,1,2,3,4,5,6,7,8,9,10,11,12,13
#define S6  0,1,2,3,4,5

__constant__ unsigned short c_arr[116] = {
    R10(0), R10(1), R14(2), R10(3), R10(4), R14(5),
    R6(6), R6(7), R6(8), R6(9), R6(10), R6(11), R6(12), R6(13) };
__constant__ unsigned short c_rank[116] = {
    XY10, XY10, Z14, XY10, XY10, Z14, K6, K6, K6, K6, K6, K6, K6, K6 };
__constant__ unsigned char c_slot[116] = {
    S10, S10, S14, S10, S10, S14, S6, S6, S6, S6, S6, S6, S6, S6 };

__global__ void __launch_bounds__(1024) select_kernel(const float* __restrict__ real_in,
                                                      const float* __restrict__ fake_in) {
    __shared__ unsigned skeys[8192];
    __shared__ int hist[2048];
    __shared__ int wtot[32], woff[32];
    __shared__ unsigned s_bin;
    __shared__ int s_rank;
    int task = blockIdx.x;
    int a = c_arr[task];
    int r = c_rank[task];
    int tid = threadIdx.x, lane = tid & 31, wid = tid >> 5;

    if (a < 6) {
        const float* src = (a < 3 ? real_in : fake_in) + (a % 3);
#pragma unroll
        for (int it = 0; it < 8; it++) {
            int idx = tid + it * 1024;
            skeys[idx] = fkey(src[idx * 3]);
        }
    } else {
        const float* src = &g_knn[0][0][0] + (a - 6) * (NP * 3);
#pragma unroll
        for (int it = 0; it < 8; it++) {
            int idx = tid + it * 1024;
            skeys[idx] = (idx < NP * 3) ? fkey(src[idx]) : 0xFFFFFFFFu;
        }
    }
    __syncthreads();

    unsigned prefix = 0;
#pragma unroll
    for (int level = 0; level < 3; level++) {
        int nb = (level < 2) ? 2048 : 1024;
        int shift = (level == 0) ? 21 : (level == 1 ? 10 : 0);
        for (int bI = tid; bI < nb; bI += 1024) hist[bI] = 0;
        __syncthreads();
#pragma unroll
        for (int it = 0; it < 8; it++) {
            unsigned k = skeys[tid + it * 1024];
            bool ok = (level == 0) ||
                      (level == 1 ? ((k >> 21) == prefix) : ((k >> 10) == prefix));
            unsigned act = __ballot_sync(0xffffffffu, ok);
            if (ok) {
                unsigned bin = (k >> shift) & (nb - 1);
                unsigned grp = __match_any_sync(act, bin);
                int ldr = __ffs(grp) - 1;
                if (lane == ldr) atomicAdd(&hist[bin], __popc(grp));
            }
        }
        __syncthreads();
        int per = nb >> 10;
        int base = tid * per;
        int local = 0;
        for (int bI = 0; bI < per; bI++) local += hist[base + bI];
        int incl = local;
#pragma unroll
        for (int off = 1; off < 32; off <<= 1) {
            int v = __shfl_up_sync(0xffffffffu, incl, off);
            if (lane >= off) incl += v;
        }
        if (lane == 31) wtot[wid] = incl;
        __syncthreads();
        if (tid < 32) {
            int v = wtot[tid];
            int inc2 = v;
#pragma unroll
            for (int off = 1; off < 32; off <<= 1) {
                int u = __shfl_up_sync(0xffffffffu, inc2, off);
                if (tid >= off) inc2 += u;
            }
            woff[tid] = inc2 - v;
        }
        __syncthreads();
        int myExcl = woff[wid] + incl - local;
        if (r >= myExcl && r < myExcl + local) {
            int rr2 = r - myExcl;
            for (int bI = 0; bI < per; bI++) {
                int h = hist[base + bI];
                if (rr2 < h) { s_bin = base + bI; s_rank = rr2; break; }
                rr2 -= h;
            }
        }
        __syncthreads();
        prefix = (prefix << ((level == 2) ? 10 : 11)) | s_bin;
        r = s_rank;
        __syncthreads();
    }
    if (tid == 0)
        g_sel[a][c_slot[task]] = unfkey(prefix);
}

// ---------------- finalize ----------------
__device__ __forceinline__ float quant_sel(int a, int k, double q, int n) {
    double pos = q * (double)(n - 1);
    int lo = (int)pos;
    float fr = (float)(pos - (double)lo);
    float vlo = g_sel[a][2 * k], vhi = g_sel[a][2 * k + 1];
    return vlo + fr * (vhi - vlo);
}

__global__ void final_kernel(const float* __restrict__ fake_in,
                             const float* __restrict__ fo,
                             float* __restrict__ out) {
    __shared__ float red[256];
    __shared__ float s_sumr, s_hex, s_feas;
    int t = threadIdx.x;

    float s = 0.0f;
    for (int i = t; i < BSZ * NP; i += 256) s += fabsf(fake_in[i * 3 + 2]);
    red[t] = s; __syncthreads();
    for (int off = 128; off; off >>= 1) { if (t < off) red[t] += red[t + off]; __syncthreads(); }
    if (t == 0) s_sumr = red[0];
    __syncthreads();

    red[t] = g_hex_partial[t]; __syncthreads();
    for (int off = 128; off; off >>= 1) { if (t < off) red[t] += red[t + off]; __syncthreads(); }
    if (t == 0) s_hex = red[0];
    __syncthreads();

    red[t] = g_feas_partial[t]; __syncthreads();
    for (int off = 128; off; off >>= 1) { if (t < off) red[t] += red[t + off]; __syncthreads(); }
    if (t == 0) s_feas = red[0];
    __syncthreads();

    if (t == 0) {
        const double q7[7] = {0.05, 0.1, 0.25, 0.5, 0.75, 0.9, 0.95};
        const double q5[5] = {0.05, 0.25, 0.5, 0.75, 0.95};
        const double q3[3] = {0.05, 0.5, 0.95};
        float loss = 0.0f;
        {   // radius loss (z): real=2, fake=5
            float acc = 0.0f;
            for (int k = 0; k < 7; k++) {
                float d = quant_sel(5, k, q7[k], 8192) - quant_sel(2, k, q7[k], 8192);
                acc += d * d;
            }
            loss += acc / 7.0f;
        }
        {   // grid density loss (x: 0/3, y: 1/4)
            float ax = 0.0f, ay = 0.0f;
            for (int k = 0; k < 5; k++) {
                float dx = quant_sel(3, k, q5[k], 8192) - quant_sel(0, k, q5[k], 8192);
                float dy = quant_sel(4, k, q5[k], 8192) - quant_sel(1, k, q5[k], 8192);
                ax += dx * dx; ay += dy * dy;
            }
            loss += 0.5f * (ax / 5.0f + ay / 5.0f);
        }
        {   // distance loss: per-batch kNN quantiles (real 6+b, fake 10+b)
            float acc = 0.0f;
            for (int b = 0; b < BSZ; b++)
                for (int k = 0; k < 3; k++) {
                    float d = quant_sel(10 + b, k, q3[k], NP * 3) -
                              quant_sel(6 + b,  k, q3[k], NP * 3);
                    acc += d * d;
                }
            loss += acc / 12.0f;
        }
        loss += -s_hex / (float)(BSZ * NP);                 // grid order
        loss += s_feas / ((float)NP * s_sumr);              // feasibility
        {   // gan loss
            float g = 0.0f;
            for (int i = 0; i < BSZ; i++) {
                float p = fo[i];
                g += 0.9f * fmaxf(logf(p), -100.0f) + 0.1f * fmaxf(logf(1.0f - p), -100.0f);
            }
            loss += -g / (float)BSZ;
        }
        out[0] = loss;
    }
}

// ---------------- launch ----------------
extern "C" void kernel_launch(void* const* d_in, const int* in_sizes, int n_in,
                              void* d_out, int out_size) {
    const float* real_in = (const float*)d_in[0];
    const float* fake_in = (const float*)d_in[1];
    const float* fo      = (const float*)d_in[2];
    float* out = (float*)d_out;

    sort_kernel  <<<8,   1024>>>(real_in, fake_in);
    pairs_kernel <<<768, 256>>>(fake_in);
    select_kernel<<<116, 1024>>>(real_in, fake_in);
    final_kernel <<<1,   256>>>(fake_in, fo, out);
}

// round 8
// speedup vs baseline: 1.1543x; 1.1543x over previous
#include <cuda_runtime.h>
#include <math_constants.h>
#include <math.h>

#define BSZ 4
#define NP  2048
#define NT  64            // 64 tiles of 32 points
#define EPSF 1e-6f
#define INF  CUDART_INF_F

// ---------------- scratch ----------------
__device__ float2 g_pos[2][BSZ][NP];      // points sorted by x: real=0, fake=1
__device__ float g_knn[2][BSZ][NP * 3];   // sqrt'd 3NN (incl self)
__device__ float g_sel[14][14];           // selected order statistics
__device__ float g_hex_partial[256];
__device__ float g_feas_partial[256];
__device__ float g_sumr[BSZ];

// ---------------- float<->sortable key ----------------
__device__ __forceinline__ unsigned fkey(float f) {
    unsigned u = __float_as_uint(f);
    return (u & 0x80000000u) ? ~u : (u | 0x80000000u);
}
__device__ __forceinline__ float unfkey(unsigned k) {
    unsigned u = (k & 0x80000000u) ? (k ^ 0x80000000u) : ~k;
    return __uint_as_float(u);
}

// ---------------- sort kernel: 8 blocks, sort each (type,batch) by x ----------------
__global__ void __launch_bounds__(1024) sort_kernel(const float* __restrict__ real_in,
                                                    const float* __restrict__ fake_in) {
    __shared__ unsigned skey[NP];
    __shared__ float sy[NP];
    int t = blockIdx.x >> 2;     // 0 real, 1 fake
    int b = blockIdx.x & 3;
    const float* base = (t ? fake_in : real_in) + b * NP * 3;
    int tid = threadIdx.x;
    for (int j = tid; j < NP; j += 1024) {
        skey[j] = fkey(base[j * 3]);
        sy[j] = base[j * 3 + 1];
    }
    __syncthreads();
    for (int k = 2; k <= NP; k <<= 1) {
        for (int jj = k >> 1; jj > 0; jj >>= 1) {
            for (int i = tid; i < NP; i += 1024) {
                int ix = i ^ jj;
                if (ix > i) {
                    unsigned ku = skey[i], kv = skey[ix];
                    bool up = ((i & k) == 0);
                    if ((ku > kv) == up) {
                        skey[i] = kv; skey[ix] = ku;
                        float yu = sy[i]; sy[i] = sy[ix]; sy[ix] = yu;
                    }
                }
            }
            __syncthreads();
        }
    }
    for (int j = tid; j < NP; j += 1024)
        g_pos[t][b][j] = make_float2(unfkey(skey[j]), sy[j]);
}

// ---------------- branch-free sorted inserts (FMNMX networks) ----------------
#define INS3(a0,a1,a2,d) do{ \
    float _m1 = fmaxf(a0,(d)), _m2 = fmaxf(a1,(d)); \
    a0 = fminf(a0,(d)); a1 = fminf(a1,_m1); a2 = fminf(a2,_m2); }while(0)

#define INS5(a0,a1,a2,a3,a4,d) do{ \
    float _m1 = fmaxf(a0,(d)), _m2 = fmaxf(a1,(d)), _m3 = fmaxf(a2,(d)), _m4 = fmaxf(a3,(d)); \
    a0 = fminf(a0,(d)); a1 = fminf(a1,_m1); a2 = fminf(a2,_m2); \
    a3 = fminf(a3,_m3); a4 = fminf(a4,_m4); }while(0)

// ---------------- warp k-min extraction ----------------
__device__ __forceinline__ float pop3(float& a0, float& a1, float& a2, int lane) {
    float bv = a0; int bl = lane;
#pragma unroll
    for (int off = 16; off; off >>= 1) {
        float ov = __shfl_down_sync(0xffffffffu, bv, off);
        int   ol = __shfl_down_sync(0xffffffffu, bl, off);
        if (ov < bv) { bv = ov; bl = ol; }
    }
    bv = __shfl_sync(0xffffffffu, bv, 0);
    bl = __shfl_sync(0xffffffffu, bl, 0);
    if (lane == bl) { a0 = a1; a1 = a2; a2 = INF; }
    return bv;
}
__device__ __forceinline__ float pop5(float& a0, float& a1, float& a2, float& a3, float& a4,
                                      int lane) {
    float bv = a0; int bl = lane;
#pragma unroll
    for (int off = 16; off; off >>= 1) {
        float ov = __shfl_down_sync(0xffffffffu, bv, off);
        int   ol = __shfl_down_sync(0xffffffffu, bl, off);
        if (ov < bv) { bv = ov; bl = ol; }
    }
    bv = __shfl_sync(0xffffffffu, bv, 0);
    bl = __shfl_sync(0xffffffffu, bl, 0);
    if (lane == bl) { a0 = a1; a1 = a2; a2 = a3; a3 = a4; a4 = INF; }
    return bv;
}

// ---------------- hex contribution (shared by loop + self-subtraction) ----------------
__device__ __forceinline__ void hex_contrib(float dx, float dy, float d2,
                                            float kth, float inv_sigma,
                                            float& wsum, float& wre, float& wim) {
    float d2e = d2 + EPSF;
    float dist = d2e * rsqrtf(d2e);
    float arg = (kth - dist) * inv_sigma;              // gate guarantees arg in (-18, ~10)
    float e = __expf(-arg);
    float w = __fdividef(1.0f, 1.0f + e);
    float c = dx;
    if (fabsf(c) < EPSF) c = c + EPSF;
    float n2 = fmaf(c, c, dy * dy);
    float inv = __fdividef(1.0f, n2);
    float un = (c * c - dy * dy) * inv;                // cos 2t
    float vn = (2.0f * c * dy) * inv;                  // sin 2t
    float re4 = un * un - vn * vn;                     // cos 4t
    float im4 = 2.0f * un * vn;                        // sin 4t
    wsum += w;
    wre = fmaf(w, re4, wre);
    wim = fmaf(w, im4, wim);
}

// ================ pairs kernel ================
// blocks [0,256): real kNN pruned; [256,512): fake kNN+hex pruned; [512,768): feas dense
__global__ void __launch_bounds__(256) pairs_kernel(const float* __restrict__ fake_in) {
    __shared__ float2 sxy[NP];
    __shared__ float srr[NP];
    __shared__ float s_acc[8];
    __shared__ float s_red[256];
    int bx = blockIdx.x;
    int warp = threadIdx.x >> 5, lane = threadIdx.x & 31;

    if (bx < 512) {
        int typ = bx >> 8;               // 0 real, 1 fake
        int bx2 = bx & 255;
        int b = bx2 >> 6;
        int i0 = ((bx2 & 63) * 8 + warp) * 4;      // 4 consecutive sorted points
        const float2* __restrict__ P = g_pos[typ][b];
        for (int j = threadIdx.x; j < NP; j += 256) sxy[j] = P[j];
        __syncthreads();
        float qx[4], qy[4];
#pragma unroll
        for (int p = 0; p < 4; p++) { float2 t = sxy[i0 + p]; qx[p] = t.x; qy[p] = t.y; }
        float qxlo = qx[0], qxhi = qx[3];          // sorted order
        int t0 = i0 >> 5;                          // home tile

        if (typ == 0) {
            // -------- real kNN: exact top-3 incl self via expanding-tile search --------
            float a[4][3];
#pragma unroll
            for (int p = 0; p < 4; p++) { a[p][0] = INF; a[p][1] = INF; a[p][2] = INF; }
#define PROC3(t) do{ \
    float2 pj = sxy[(t) * 32 + lane]; \
    _Pragma("unroll") \
    for (int p = 0; p < 4; p++) { \
        float dx = qx[p] - pj.x, dy = qy[p] - pj.y; \
        float d2 = fmaf(dx, dx, dy * dy); \
        INS3(a[p][0], a[p][1], a[p][2], d2); } }while(0)
            PROC3(t0);
            int tR = t0 + 1, tL = t0 - 1;
            while (true) {
                // T = valid upper bound on every point's true 3rd-min:
                // min over lanes of (max over p of a2) >= min_lane a2[p] >= true3rd(p)
                float lmax = fmaxf(fmaxf(a[0][2], a[1][2]), fmaxf(a[2][2], a[3][2]));
                unsigned m = __reduce_min_sync(0xffffffffu, __float_as_uint(lmax));
                float T = __uint_as_float(m);
                bool okR = false, okL = false;
                if (tR < NT) { float g = sxy[tR * 32].x - qxhi;      okR = (g * g <= T); }
                if (tL >= 0) { float g = qxlo - sxy[tL * 32 + 31].x; okL = (g * g <= T); }
                if (!okR && !okL) break;
                if (okR) { PROC3(tR); tR++; }
                if (okL) { PROC3(tL); tL--; }
            }
#pragma unroll
            for (int p = 0; p < 4; p++) {
                float o0 = pop3(a[p][0], a[p][1], a[p][2], lane);
                float o1 = pop3(a[p][0], a[p][1], a[p][2], lane);
                float o2 = pop3(a[p][0], a[p][1], a[p][2], lane);
                if (lane == 0) {
                    float* dst = &g_knn[0][b][(i0 + p) * 3];
                    dst[0] = sqrtf(o0 + EPSF); dst[1] = sqrtf(o1 + EPSF); dst[2] = sqrtf(o2 + EPSF);
                }
            }
        } else {
            // -------- fake: exact top-5 incl self (kNN + kth), then weighted pass --------
            float a[4][5];
#pragma unroll
            for (int p = 0; p < 4; p++)
                { a[p][0]=INF; a[p][1]=INF; a[p][2]=INF; a[p][3]=INF; a[p][4]=INF; }
#define PROC5(t) do{ \
    float2 pj = sxy[(t) * 32 + lane]; \
    _Pragma("unroll") \
    for (int p = 0; p < 4; p++) { \
        float dx = qx[p] - pj.x, dy = qy[p] - pj.y; \
        float d2 = fmaf(dx, dx, dy * dy); \
        INS5(a[p][0], a[p][1], a[p][2], a[p][3], a[p][4], d2); } }while(0)
            PROC5(t0);
            int tR = t0 + 1, tL = t0 - 1;
            while (true) {
                float lmax = fmaxf(fmaxf(a[0][4], a[1][4]), fmaxf(a[2][4], a[3][4]));
                unsigned m = __reduce_min_sync(0xffffffffu, __float_as_uint(lmax));
                float T = __uint_as_float(m);
                bool okR = false, okL = false;
                if (tR < NT) { float g = sxy[tR * 32].x - qxhi;      okR = (g * g <= T); }
                if (tL >= 0) { float g = qxlo - sxy[tL * 32 + 31].x; okL = (g * g <= T); }
                if (!okR && !okL) break;
                if (okR) { PROC5(tR); tR++; }
                if (okL) { PROC5(tL); tL--; }
            }
            float kth[4], isg[4], lim2[4];
#pragma unroll
            for (int p = 0; p < 4; p++) {
                float o0 = pop5(a[p][0], a[p][1], a[p][2], a[p][3], a[p][4], lane);
                float o1 = pop5(a[p][0], a[p][1], a[p][2], a[p][3], a[p][4], lane);
                float o2 = pop5(a[p][0], a[p][1], a[p][2], a[p][3], a[p][4], lane);
                float o3 = pop5(a[p][0], a[p][1], a[p][2], a[p][3], a[p][4], lane); (void)o3;
                float o4 = pop5(a[p][0], a[p][1], a[p][2], a[p][3], a[p][4], lane);
                if (lane == 0) {   // kNN incl self: o0=0(self), o1, o2
                    float* dst = &g_knn[1][b][(i0 + p) * 3];
                    dst[0] = sqrtf(o0 + EPSF); dst[1] = sqrtf(o1 + EPSF); dst[2] = sqrtf(o2 + EPSF);
                }
                float kv = sqrtf(o4 + EPSF);       // 4th non-self neighbor
                float sg = fmaxf(0.1f * fmaxf(kv, EPSF), EPSF);
                kth[p] = kv;
                isg[p] = __fdividef(1.0f, sg);
                float lim = kv + 18.0f * sg;       // beyond: w <= sigmoid(-18), negligible
                lim2[p] = fmaf(lim, lim, -EPSF);
            }
            // pass 2: weighted orientation sums, pruned by fixed radius
            float ws[4] = {0.f,0.f,0.f,0.f}, wr[4] = {0.f,0.f,0.f,0.f}, wi[4] = {0.f,0.f,0.f,0.f};
            float T2 = fmaxf(fmaxf(lim2[0], lim2[1]), fmaxf(lim2[2], lim2[3]));
#define PROCH(t) do{ \
    float2 pj = sxy[(t) * 32 + lane]; \
    _Pragma("unroll") \
    for (int p = 0; p < 4; p++) { \
        float dx = qx[p] - pj.x, dy = qy[p] - pj.y; \
        float d2 = fmaf(dx, dx, dy * dy); \
        if (d2 <= lim2[p]) hex_contrib(dx, dy, d2, kth[p], isg[p], ws[p], wr[p], wi[p]); } }while(0)
            PROCH(t0);
            tR = t0 + 1; tL = t0 - 1;
            while (true) {
                bool okR = false, okL = false;
                if (tR < NT) { float g = sxy[tR * 32].x - qxhi;      okR = (g * g <= T2); }
                if (tL >= 0) { float g = qxlo - sxy[tL * 32 + 31].x; okL = (g * g <= T2); }
                if (!okR && !okL) break;
                if (okR) { PROCH(tR); tR++; }
                if (okL) { PROCH(tL); tL--; }
            }
#pragma unroll
            for (int p = 0; p < 4; p++) {
#pragma unroll
                for (int off = 16; off; off >>= 1) {
                    ws[p] += __shfl_down_sync(0xffffffffu, ws[p], off);
                    wr[p] += __shfl_down_sync(0xffffffffu, wr[p], off);
                    wi[p] += __shfl_down_sync(0xffffffffu, wi[p], off);
                }
            }
            if (lane == 0) {
                float psum = 0.0f;
#pragma unroll
                for (int p = 0; p < 4; p++) {
                    float ss = 0.0f, sr = 0.0f, si = 0.0f;   // subtract self exactly once
                    hex_contrib(0.0f, 0.0f, 0.0f, kth[p], isg[p], ss, sr, si);
                    float wsum = ws[p] - ss, wre = wr[p] - sr, wim = wi[p] - si;
                    psum += sqrtf(wre * wre + wim * wim) / fmaxf(wsum, EPSF);
                }
                s_acc[warp] = psum;
            }
            __syncthreads();
            if (threadIdx.x == 0) {
                float s = 0.0f;
                for (int w = 0; w < 8; w++) s += s_acc[w];
                g_hex_partial[bx2] = s;
            }
        }
    } else {
        // -------- feasibility: dense lower triangle (original order), 4 rows/warp --------
        int bx2 = bx - 512;
        int b = bx2 >> 6;
        int ibase = (bx2 & 63) * 32;
        const float* base = fake_in + b * NP * 3;
        for (int j = threadIdx.x; j < NP; j += 256) {
            sxy[j] = make_float2(base[j * 3], base[j * 3 + 1]);
            srr[j] = fabsf(base[j * 3 + 2]);
        }
        __syncthreads();
        // one block per batch also computes sum|r| (deterministic order)
        if ((bx2 & 63) == 0) {
            float s = 0.0f;
            for (int j = threadIdx.x; j < NP; j += 256) s += srr[j];
            s_red[threadIdx.x] = s; __syncthreads();
            for (int off = 128; off; off >>= 1) {
                if (threadIdx.x < off) s_red[threadIdx.x] += s_red[threadIdx.x + off];
                __syncthreads();
            }
            if (threadIdx.x == 0) g_sumr[b] = s_red[0];
        }
        float qx[4], qy[4], ri[4];
        int i0 = ibase + warp * 4;
#pragma unroll
        for (int p = 0; p < 4; p++) {
            float2 pp = sxy[i0 + p];
            qx[p] = pp.x; qy[p] = pp.y;
            ri[p] = srr[i0 + p] - 1e-4f;
        }
        float acc = 0.0f;
        int imax = i0 + 3;
        for (int j = lane; j < imax; j += 32) {
            float2 pj = sxy[j];
            float rj = srr[j];
#pragma unroll
            for (int p = 0; p < 4; p++) {
                if (j < i0 + p) {                      // strict lower triangle
                    float dx = qx[p] - pj.x, dy = qy[p] - pj.y;
                    float sq = fmaf(dx, dx, dy * dy);
                    float thr = ri[p] + rj;
                    if (sq > 0.0f && thr > 0.0f && sq < thr * thr)
                        acc += thr - sq * rsqrtf(sq);
                }
            }
        }
#pragma unroll
        for (int off = 16; off; off >>= 1)
            acc += __shfl_down_sync(0xffffffffu, acc, off);
        if (lane == 0) s_acc[warp] = acc;
        __syncthreads();
        if (threadIdx.x == 0) {
            float s = 0.0f;
            for (int w = 0; w < 8; w++) s += s_acc[w];
            g_feas_partial[bx2] = s;
        }
    }
}

// ---------------- radix select: one block per (array, rank), 1024 thr ----------------
#define XY10 409,410,2047,2048,4095,4096,6143,6144,7781,7782
#define Z14  409,410,819,820,2047,2048,4095,4096,6143,6144,7371,7372,7781,7782
#define K6   307,308,3071,3072,5835,5836
#define R10(x) x,x,x,x,x,x,x,x,x,x
#define R14(x) x,x,x,x,x,x,x,x,x,x,x,x,x,x
#define R6(x)  x,x,x,x,x,x
#define S10 0,1,2,3,4,5,6,7,8,9
#define S14 0,1,2,3,4,5,6,7,8,9,10,11,12,13
#define S6  0,1,2,3,4,5

__constant__ unsigned short c_arr[116] = {
    R10(0), R10(1), R14(2), R10(3), R10(4), R14(5),
    R6(6), R6(7), R6(8), R6(9), R6(10), R6(11), R6(12), R6(13) };
__constant__ unsigned short c_rank[116] = {
    XY10, XY10, Z14, XY10, XY10, Z14, K6, K6, K6, K6, K6, K6, K6, K6 };
__constant__ unsigned char c_slot[116] = {
    S10, S10, S14, S10, S10, S14, S6, S6, S6, S6, S6, S6, S6, S6 };

__global__ void __launch_bounds__(1024) select_kernel(const float* __restrict__ real_in,
                                                      const float* __restrict__ fake_in) {
    __shared__ unsigned skeys[8192];
    __shared__ int hist[2048];
    __shared__ int wtot[32], woff[32];
    __shared__ unsigned s_bin;
    __shared__ int s_rank;
    int task = blockIdx.x;
    int a = c_arr[task];
    int r = c_rank[task];
    int tid = threadIdx.x, lane = tid & 31, wid = tid >> 5;

    if (a < 6) {
        const float* src = (a < 3 ? real_in : fake_in) + (a % 3);
#pragma unroll
        for (int it = 0; it < 8; it++) {
            int idx = tid + it * 1024;
            skeys[idx] = fkey(src[idx * 3]);
        }
    } else {
        const float* src = &g_knn[0][0][0] + (a - 6) * (NP * 3);
#pragma unroll
        for (int it = 0; it < 8; it++) {
            int idx = tid + it * 1024;
            skeys[idx] = (idx < NP * 3) ? fkey(src[idx]) : 0xFFFFFFFFu;
        }
    }
    __syncthreads();

    unsigned prefix = 0;
#pragma unroll
    for (int level = 0; level < 3; level++) {
        int nb = (level < 2) ? 2048 : 1024;
        int shift = (level == 0) ? 21 : (level == 1 ? 10 : 0);
        for (int bI = tid; bI < nb; bI += 1024) hist[bI] = 0;
        __syncthreads();
#pragma unroll
        for (int it = 0; it < 8; it++) {
            unsigned k = skeys[tid + it * 1024];
            bool ok = (level == 0) ||
                      (level == 1 ? ((k >> 21) == prefix) : ((k >> 10) == prefix));
            unsigned act = __ballot_sync(0xffffffffu, ok);
            if (ok) {
                unsigned bin = (k >> shift) & (nb - 1);
                unsigned grp = __match_any_sync(act, bin);
                int ldr = __ffs(grp) - 1;
                if (lane == ldr) atomicAdd(&hist[bin], __popc(grp));
            }
        }
        __syncthreads();
        int per = nb >> 10;
        int base = tid * per;
        int local = 0;
        for (int bI = 0; bI < per; bI++) local += hist[base + bI];
        int incl = local;
#pragma unroll
        for (int off = 1; off < 32; off <<= 1) {
            int v = __shfl_up_sync(0xffffffffu, incl, off);
            if (lane >= off) incl += v;
        }
        if (lane == 31) wtot[wid] = incl;
        __syncthreads();
        if (tid < 32) {
            int v = wtot[tid];
            int inc2 = v;
#pragma unroll
            for (int off = 1; off < 32; off <<= 1) {
                int u = __shfl_up_sync(0xffffffffu, inc2, off);
                if (tid >= off) inc2 += u;
            }
            woff[tid] = inc2 - v;
        }
        __syncthreads();
        int myExcl = woff[wid] + incl - local;
        if (r >= myExcl && r < myExcl + local) {
            int rr2 = r - myExcl;
            for (int bI = 0; bI < per; bI++) {
                int h = hist[base + bI];
                if (rr2 < h) { s_bin = base + bI; s_rank = rr2; break; }
                rr2 -= h;
            }
        }
        __syncthreads();
        prefix = (prefix << ((level == 2) ? 10 : 11)) | s_bin;
        r = s_rank;
        __syncthreads();
    }
    if (tid == 0)
        g_sel[a][c_slot[task]] = unfkey(prefix);
}

// ---------------- finalize ----------------
__device__ __forceinline__ float quant_sel(int a, int k, double q, int n) {
    double pos = q * (double)(n - 1);
    int lo = (int)pos;
    float fr = (float)(pos - (double)lo);
    float vlo = g_sel[a][2 * k], vhi = g_sel[a][2 * k + 1];
    return vlo + fr * (vhi - vlo);
}

__global__ void final_kernel(const float* __restrict__ fo,
                             float* __restrict__ out) {
    __shared__ float red[256];
    __shared__ float s_hex, s_feas;
    int t = threadIdx.x;

    red[t] = g_hex_partial[t]; __syncthreads();
    for (int off = 128; off; off >>= 1) { if (t < off) red[t] += red[t + off]; __syncthreads(); }
    if (t == 0) s_hex = red[0];
    __syncthreads();

    red[t] = g_feas_partial[t]; __syncthreads();
    for (int off = 128; off; off >>= 1) { if (t < off) red[t] += red[t + off]; __syncthreads(); }
    if (t == 0) s_feas = red[0];
    __syncthreads();

    if (t == 0) {
        float s_sumr = g_sumr[0] + g_sumr[1] + g_sumr[2] + g_sumr[3];
        const double q7[7] = {0.05, 0.1, 0.25, 0.5, 0.75, 0.9, 0.95};
        const double q5[5] = {0.05, 0.25, 0.5, 0.75, 0.95};
        const double q3[3] = {0.05, 0.5, 0.95};
        float loss = 0.0f;
        {   // radius loss (z): real=2, fake=5
            float acc = 0.0f;
            for (int k = 0; k < 7; k++) {
                float d = quant_sel(5, k, q7[k], 8192) - quant_sel(2, k, q7[k], 8192);
                acc += d * d;
            }
            loss += acc / 7.0f;
        }
        {   // grid density loss (x: 0/3, y: 1/4)
            float ax = 0.0f, ay = 0.0f;
            for (int k = 0; k < 5; k++) {
                float dx = quant_sel(3, k, q5[k], 8192) - quant_sel(0, k, q5[k], 8192);
                float dy = quant_sel(4, k, q5[k], 8192) - quant_sel(1, k, q5[k], 8192);
                ax += dx * dx; ay += dy * dy;
            }
            loss += 0.5f * (ax / 5.0f + ay / 5.0f);
        }
        {   // distance loss: per-batch kNN quantiles (real 6+b, fake 10+b)
            float acc = 0.0f;
            for (int b = 0; b < BSZ; b++)
                for (int k = 0; k < 3; k++) {
                    float d = quant_sel(10 + b, k, q3[k], NP * 3) -
                              quant_sel(6 + b,  k, q3[k], NP * 3);
                    acc += d * d;
                }
            loss += acc / 12.0f;
        }
        loss += -s_hex / (float)(BSZ * NP);                 // grid order
        loss += s_feas / ((float)NP * s_sumr);              // feasibility
        {   // gan loss
            float g = 0.0f;
            for (int i = 0; i < BSZ; i++) {
                float p = fo[i];
                g += 0.9f * fmaxf(logf(p), -100.0f) + 0.1f * fmaxf(logf(1.0f - p), -100.0f);
            }
            loss += -g / (float)BSZ;
        }
        out[0] = loss;
    }
}

// ---------------- launch ----------------
extern "C" void kernel_launch(void* const* d_in, const int* in_sizes, int n_in,
                              void* d_out, int out_size) {
    const float* real_in = (const float*)d_in[0];
    const float* fake_in = (const float*)d_in[1];
    const float* fo      = (const float*)d_in[2];
    float* out = (float*)d_out;

    sort_kernel  <<<8,   1024>>>(real_in, fake_in);
    pairs_kernel <<<768, 256>>>(fake_in);
    select_kernel<<<116, 1024>>>(real_in, fake_in);
    final_kernel <<<1,   256>>>(fo, out);
}